// round 3
// baseline (speedup 1.0000x reference)
#include <cuda_runtime.h>
#include <math.h>

// FLIF fractional LIF neuron forward pass.
// S=2048 neurons (independent), T=384 sequential steps per neuron.
// memory[n] = sum_{j=1}^{n-1} wr[n-j] * delta_j  (delta_j = V_j - V_{j-1})
// Strategy: warp per neuron, forward-SCATTER the memory convolution into
// register-resident future slots (lane l owns timesteps l+32k) -> only one
// shfl per step on the critical chain, no warp reduction.

#define T_STEPS 384
#define WARPS   4
#define KPL     12   // T_STEPS / 32 register slots per lane

__global__ __launch_bounds__(WARPS * 32) void flif_kernel(
    const float* __restrict__ I,      // [S, T] row-major
    const float* __restrict__ Wt,     // weights, length Wlen (=4999)
    float* __restrict__ out,          // [2, S, T]: spikes then trace
    int S, int Wlen, float COEF)
{
    __shared__ float wr_sh[T_STEPS + 1];           // wr[a] = Wt[Wlen - a], wr[0]=0
    __shared__ float io_sh[WARPS][T_STEPS];        // input row, overwritten by trace
    __shared__ float spk_sh[WARPS][T_STEPS];

    const int tid  = threadIdx.x;
    const int w    = tid >> 5;
    const int lane = tid & 31;
    const int s0   = blockIdx.x * WARPS;
    const int s    = s0 + w;

    // Load wr table (wr[0] = 0; wr[a] = weights[::-1][a-1] = Wt[Wlen - a])
    for (int idx = tid; idx <= T_STEPS; idx += WARPS * 32)
        wr_sh[idx] = (idx == 0) ? 0.0f : Wt[Wlen - idx];

    // Load this block's input rows (contiguous in global) into shared
    {
        int total = (S - s0) * T_STEPS;
        if (total > WARPS * T_STEPS) total = WARPS * T_STEPS;
        const float* src = I + (size_t)s0 * T_STEPS;
        float* dst = &io_sh[0][0];
        for (int idx = tid; idx < total; idx += WARPS * 32)
            dst[idx] = src[idx];
    }
    __syncthreads();

    if (s < S) {
        // M[k] at lane l = accumulated memory term for timestep (l + 32k)
        float M[KPL];
        #pragma unroll
        for (int k = 0; k < KPL; ++k) M[k] = 0.0f;

        float V = 0.0f;  // V_trace init

        #pragma unroll
        for (int p = 0; p < KPL; ++p) {       // phase p covers n in [32p, 32p+32)
            #pragma unroll 4
            for (int i = 0; i < 32; ++i) {
                const int n = p * 32 + i;

                // memory term for step n lives in lane (n&31), register M[p]
                float mem = __shfl_sync(0xffffffffu, M[p], i);
                float In  = io_sh[w][n];

                // spike uses PREVIOUS V, strict >
                float spike = (V > -50.0f) ? 1.0f : 0.0f;

                // N >= 2 branch (default)
                float Vpre = fmaf(COEF, fmaf(-0.025f, V + 70.0f, In), V) - mem;
                if (n == 1) Vpre = V + 0.005f * (-V + In * 40.0f);  // N == 1 branch
                if (n == 0) Vpre = -70.0f;                          // N == 0 branch

                float Vnew  = Vpre - spike * 20.0f;   // detached reset: spike*(THRESH-V_RESET)
                float delta = Vnew - V;

                if (lane == i) {
                    io_sh[w][n]  = Vnew;   // trace overwrites consumed input
                    spk_sh[w][n] = spike;
                }

                // scatter delta_n into all FUTURE owned slots (t > n); n==0 delta masked
                if (n >= 1) {
                    #pragma unroll
                    for (int k = 0; k < KPL; ++k) {
                        int t = lane + 32 * k;
                        if (t > n) M[k] = fmaf(wr_sh[t - n], delta, M[k]);
                    }
                }
                V = Vnew;
            }
        }
        __syncwarp();

        // Coalesced dump: spikes at [0, S*T), trace at [S*T, 2*S*T)
        const size_t base  = (size_t)s * T_STEPS;
        const size_t troff = (size_t)S * T_STEPS;
        for (int t = lane; t < T_STEPS; t += 32) {
            out[base + t]         = spk_sh[w][t];
            out[troff + base + t] = io_sh[w][t];
        }
    }
}

extern "C" void kernel_launch(void* const* d_in, const int* in_sizes, int n_in,
                              void* d_out, int out_size)
{
    const float* I  = (const float*)d_in[0];
    const float* Wt = (const float*)d_in[1];
    float* out = (float*)d_out;

    const int S    = in_sizes[0] / T_STEPS;
    const int Wlen = in_sizes[1];

    // COEF = dt^alpha * Gamma(2 - alpha) / Cm, computed in double like the reference
    const float coef = (float)(pow(0.1, 0.15) * tgamma(2.0 - 0.15) / 0.5);

    const int blocks = (S + WARPS - 1) / WARPS;
    flif_kernel<<<blocks, WARPS * 32>>>(I, Wt, out, S, Wlen, coef);
}

// round 4
// speedup vs baseline: 1.1556x; 1.1556x over previous
#include <cuda_runtime.h>
#include <math.h>

// FLIF fractional LIF forward pass — round 4.
// Warp per neuron, lane l owns timesteps l+32k (register slots M[k]).
// Phase-peeled scatter: at phase p, slots k>p are scattered with NO predicate
// and a single shared-address base (lane - i) with immediate offsets; slot
// k==p uses the one remaining (lane > i) guard. Outputs latched in registers
// (lane i keeps step 32p+i), written coalesced at the end — no output smem.

#define T_STEPS 384
#define WARPS   4
#define KPL     12   // T_STEPS / 32 register slots per lane

__global__ __launch_bounds__(WARPS * 32) void flif_kernel(
    const float* __restrict__ I,      // [S, T] row-major
    const float* __restrict__ Wt,     // weights, length Wlen
    float* __restrict__ out,          // [2, S, T]: spikes then trace
    int S, int Wlen, float COEF)
{
    __shared__ float wr_sh[T_STEPS + 1];     // wr[a] = Wt[Wlen - a], wr[0]=0
    __shared__ float in_sh[WARPS][T_STEPS];  // staged input rows

    const int tid  = threadIdx.x;
    const int w    = tid >> 5;
    const int lane = tid & 31;
    const int s0   = blockIdx.x * WARPS;
    const int s    = s0 + w;

    for (int idx = tid; idx <= T_STEPS; idx += WARPS * 32)
        wr_sh[idx] = (idx == 0) ? 0.0f : Wt[Wlen - idx];

    {
        int total = (S - s0) * T_STEPS;
        if (total > WARPS * T_STEPS) total = WARPS * T_STEPS;
        const float* src = I + (size_t)s0 * T_STEPS;
        float* dst = &in_sh[0][0];
        for (int idx = tid; idx < total; idx += WARPS * 32)
            dst[idx] = src[idx];
    }
    __syncthreads();

    if (s >= S) return;

    float M[KPL];
    #pragma unroll
    for (int k = 0; k < KPL; ++k) M[k] = 0.0f;
    float trc_r[KPL];
    float spk_r[KPL];
    float V = 0.0f;                      // V_trace init

    const float* wrow = in_sh[w];

    // ---- phase 0: carries the n==0 / n==1 special branches ----
    {
        #pragma unroll 4
        for (int i = 0; i < 32; ++i) {
            float mem = __shfl_sync(0xffffffffu, M[0], i);
            float In  = wrow[i];
            float spike = (V > -50.0f) ? 1.0f : 0.0f;       // spike uses PREVIOUS V
            float Vpre = fmaf(COEF, fmaf(-0.025f, V + 70.0f, In), V) - mem;
            if (i == 1) Vpre = V + 0.005f * (-V + In * 40.0f);  // N == 1 branch
            if (i == 0) Vpre = -70.0f;                          // N == 0 branch
            float Vnew  = fmaf(spike, -20.0f, Vpre);        // detached reset
            float delta = Vnew - V;
            if (i == lane) { trc_r[0] = Vnew; spk_r[0] = spike; }
            if (i >= 1) {                                   // delta_0 never enters memory
                const int a = lane - i;
                if (lane > i) M[0] = fmaf(wr_sh[a], delta, M[0]);
                #pragma unroll
                for (int k = 1; k < KPL; ++k)
                    M[k] = fmaf(wr_sh[a + 32 * k], delta, M[k]);
            }
            V = Vnew;
        }
    }

    // ---- phases 1..11: branch-free core, predicate-free far scatter ----
    #pragma unroll
    for (int p = 1; p < KPL; ++p) {
        #pragma unroll 4
        for (int i = 0; i < 32; ++i) {
            float mem = __shfl_sync(0xffffffffu, M[p], i);
            float In  = wrow[p * 32 + i];
            float spike = (V > -50.0f) ? 1.0f : 0.0f;
            float Vpre = fmaf(COEF, fmaf(-0.025f, V + 70.0f, In), V) - mem;
            float Vnew  = fmaf(spike, -20.0f, Vpre);
            float delta = Vnew - V;
            if (i == lane) { trc_r[p] = Vnew; spk_r[p] = spike; }
            const int a = lane - i;
            if (lane > i) M[p] = fmaf(wr_sh[a], delta, M[p]);  // same-phase slots
            #pragma unroll
            for (int k = p + 1; k < KPL; ++k)                  // strictly-future slots
                M[k] = fmaf(wr_sh[a + 32 * (k - p)], delta, M[k]);
            V = Vnew;
        }
    }

    // Coalesced register dump: lane l holds times 32p + l.
    const size_t base  = (size_t)s * T_STEPS;
    const size_t troff = (size_t)S * T_STEPS;
    #pragma unroll
    for (int p = 0; p < KPL; ++p) {
        out[base + p * 32 + lane]         = spk_r[p];
        out[troff + base + p * 32 + lane] = trc_r[p];
    }
}

extern "C" void kernel_launch(void* const* d_in, const int* in_sizes, int n_in,
                              void* d_out, int out_size)
{
    const float* I  = (const float*)d_in[0];
    const float* Wt = (const float*)d_in[1];
    float* out = (float*)d_out;

    const int S    = in_sizes[0] / T_STEPS;
    const int Wlen = in_sizes[1];

    // COEF = dt^alpha * Gamma(2 - alpha) / Cm, computed in double like the reference
    const float coef = (float)(pow(0.1, 0.15) * tgamma(2.0 - 0.15) / 0.5);

    const int blocks = (S + WARPS - 1) / WARPS;
    flif_kernel<<<blocks, WARPS * 32>>>(I, Wt, out, S, Wlen, coef);
}

// round 5
// speedup vs baseline: 1.4804x; 1.2810x over previous
#include <cuda_runtime.h>
#include <math.h>

// FLIF fractional LIF — round 5.
// Rotating age-ownership + f32x2 packing (2 neurons/thread).
// Lane l owns ages {12l+1 .. 12l+12}; wr coefficients are STATIC registers
// (zero wr LDS in the loop). Accumulators form a 12-deep cyclic buffer:
// per step, slot M[n%12] is consumed (dest n, lane 0), handed one lane down
// via a single 64-bit shfl, and refilled as the new tail. Scatter = 12
// fma.rn.f32x2 with compile-time slot/weight indices.

#define T_STEPS 384
typedef unsigned long long u64;

__device__ __forceinline__ u64 pack2(float x, float y) {
    u64 r; asm("mov.b64 %0, {%1, %2};" : "=l"(r) : "f"(x), "f"(y)); return r;
}
__device__ __forceinline__ void unpack2(u64 a, float& x, float& y) {
    asm("mov.b64 {%0, %1}, %2;" : "=f"(x), "=f"(y) : "l"(a));
}
__device__ __forceinline__ u64 fma2(u64 a, u64 b, u64 c) {
    u64 d; asm("fma.rn.f32x2 %0, %1, %2, %3;" : "=l"(d) : "l"(a), "l"(b), "l"(c)); return d;
}
__device__ __forceinline__ u64 add2(u64 a, u64 b) {
    u64 d; asm("add.rn.f32x2 %0, %1, %2;" : "=l"(d) : "l"(a), "l"(b)); return d;
}

struct St {
    u64 M[12];      // negated-memory accumulators (cyclic by age)
    u64 wrn[12];    // wrn[m] = (-wr[12*lane+m+1]) packed in both halves
    u64 cA, cG, cC; // (-1.75,-1.75), (-0.025,-0.025), (COEF,COEF)
    float Vlo, Vhi;
    bool is0, is31;
    int lnext;
};

// One uniform step for n >= 2.  RR = n % 12 (compile-time).
// Entry invariant: logical age-slot m sits at physical (m + n) % 12 and holds
// the negated partial sum for destination n + 12*lane + m.
template<int RR>
__device__ __forceinline__ void step(St& s, const float2* __restrict__ inw,
                                     float2* __restrict__ trcw, int idx)
{
    u64 mem2 = __shfl_sync(0xffffffffu, s.M[RR], 0);        // dest n (complete)
    u64 tmp  = __shfl_sync(0xffffffffu, s.M[RR], s.lnext);  // handoff lane+1 -> lane

    float2 In = inw[idx];
    u64 a2  = add2(pack2(In.x, In.y), s.cA);   // In - 1.75
    u64 V2  = pack2(s.Vlo, s.Vhi);
    u64 t2  = fma2(V2, s.cG, a2);              // -0.025*V + In - 1.75
    u64 u2  = fma2(t2, s.cC, V2);              // COEF*(...) + V
    u64 vp2 = add2(u2, mem2);                  // + (negated memory) == - memory

    float vpl, vph; unpack2(vp2, vpl, vph);
    float rl = (s.Vlo > -50.0f) ? 20.0f : 0.0f;   // spike uses PREVIOUS V
    float rh = (s.Vhi > -50.0f) ? 20.0f : 0.0f;
    float vnl = vpl - rl;
    float vnh = vph - rh;
    u64 d2 = pack2(vnl - s.Vlo, vnh - s.Vhi);     // delta_n (both neurons)

    // cyclic shift: consumed slot becomes new tail (age 12*lane+12);
    // lane 31's fresh tail (dest n+384) starts at zero.
    s.M[RR] = s.is31 ? 0ull : tmp;

    // scatter delta_n: physical slot j holds logical m = (j - n - 1) mod 12
#pragma unroll
    for (int j = 0; j < 12; ++j)
        s.M[j] = fma2(s.wrn[(j + 11 - RR) % 12], d2, s.M[j]);

    if (s.is0) trcw[idx] = make_float2(vnl, vnh);
    s.Vlo = vnl; s.Vhi = vnh;
}

__global__ __launch_bounds__(32) void flif_kernel(
    const float* __restrict__ I,    // [S, T]
    const float* __restrict__ Wt,   // weights, length Wlen
    float* __restrict__ out,        // [2, S, T]: spikes then trace
    int S, int Wlen, float COEF)
{
    __shared__ float2 in_sh[T_STEPS];
    __shared__ float2 trc_sh[T_STEPS];

    const int lane = threadIdx.x & 31;
    const int pair = blockIdx.x;            // one warp-block per neuron pair
    const int sA = pair * 2, sB = sA + 1;

    // stage the two input rows interleaved
    const float* rowA = I + (size_t)sA * T_STEPS;
    const float* rowB = I + (size_t)sB * T_STEPS;
    for (int t = lane; t < T_STEPS; t += 32)
        in_sh[t] = make_float2(rowA[t], rowB[t]);
    __syncwarp();

    St s;
    s.is0 = (lane == 0);
    s.is31 = (lane == 31);
    s.lnext = (lane + 1) & 31;
    s.cA = pack2(-1.75f, -1.75f);
    s.cG = pack2(-0.025f, -0.025f);
    s.cC = pack2(COEF, COEF);
#pragma unroll
    for (int m = 0; m < 12; ++m) {
        float v = -Wt[Wlen - (12 * lane + m + 1)];   // -wr[12*lane+m+1]
        s.wrn[m] = pack2(v, v);
    }
#pragma unroll
    for (int j = 0; j < 12; ++j) s.M[j] = 0ull;

    // ---- step 0 (exact): V_prev=0 -> spike=1, Vpre=-70, Vnew=-90; delta_0 NOT scattered
    s.Vlo = -90.0f; s.Vhi = -90.0f;
    if (s.is0) trc_sh[0] = make_float2(-90.0f, -90.0f);

    // ---- step 1 (exact reference arithmetic): V1 = V + 0.005*(-V + I*40); spike=0; mem=0
    {
        float2 In = in_sh[1];
        float vnl = s.Vlo + 0.005f * (-s.Vlo + In.x * 40.0f);
        float vnh = s.Vhi + 0.005f * (-s.Vhi + In.y * 40.0f);
        u64 d2 = pack2(vnl - s.Vlo, vnh - s.Vhi);
        // scatter delta_1 (r = 1): physical j holds logical m = (j - 2) mod 12
#pragma unroll
        for (int j = 0; j < 12; ++j)
            s.M[j] = fma2(s.wrn[(j + 10) % 12], d2, s.M[j]);
        s.Vlo = vnl; s.Vhi = vnh;
        if (s.is0) trc_sh[1] = make_float2(vnl, vnh);
    }

    // ---- main loop: n = 2 .. 373, 31 iterations of 12 steps (r = n%12 = 2,3,..,11,0,1)
#define BODY12(NB)                              \
    step<2>(s, in_sh, trc_sh, (NB) + 0);        \
    step<3>(s, in_sh, trc_sh, (NB) + 1);        \
    step<4>(s, in_sh, trc_sh, (NB) + 2);        \
    step<5>(s, in_sh, trc_sh, (NB) + 3);        \
    step<6>(s, in_sh, trc_sh, (NB) + 4);        \
    step<7>(s, in_sh, trc_sh, (NB) + 5);        \
    step<8>(s, in_sh, trc_sh, (NB) + 6);        \
    step<9>(s, in_sh, trc_sh, (NB) + 7);        \
    step<10>(s, in_sh, trc_sh, (NB) + 8);       \
    step<11>(s, in_sh, trc_sh, (NB) + 9);       \
    step<0>(s, in_sh, trc_sh, (NB) + 10);       \
    step<1>(s, in_sh, trc_sh, (NB) + 11);

    for (int nb = 2; nb <= T_STEPS - 22; nb += 12) {   // nb = 2,14,...,362
        BODY12(nb)
    }
    // ---- epilogue: n = 374..383 (r = 2..11)
    step<2>(s, in_sh, trc_sh, 374);
    step<3>(s, in_sh, trc_sh, 375);
    step<4>(s, in_sh, trc_sh, 376);
    step<5>(s, in_sh, trc_sh, 377);
    step<6>(s, in_sh, trc_sh, 378);
    step<7>(s, in_sh, trc_sh, 379);
    step<8>(s, in_sh, trc_sh, 380);
    step<9>(s, in_sh, trc_sh, 381);
    step<10>(s, in_sh, trc_sh, 382);
    step<11>(s, in_sh, trc_sh, 383);
#undef BODY12

    __syncwarp();

    // ---- dump: trace directly; spikes derived from trace[t-1] (spike_t = V_{t-1} > -50)
    const size_t baseA = (size_t)sA * T_STEPS;
    const size_t baseB = (size_t)sB * T_STEPS;
    const size_t off   = (size_t)S * T_STEPS;
    for (int t = lane; t < T_STEPS; t += 32) {
        float2 v = trc_sh[t];
        out[off + baseA + t] = v.x;
        out[off + baseB + t] = v.y;
        float sl, sh;
        if (t == 0) { sl = 1.0f; sh = 1.0f; }   // V_prev = 0 > -50
        else {
            float2 vp = trc_sh[t - 1];
            sl = (vp.x > -50.0f) ? 1.0f : 0.0f;
            sh = (vp.y > -50.0f) ? 1.0f : 0.0f;
        }
        out[baseA + t] = sl;
        out[baseB + t] = sh;
    }
}

extern "C" void kernel_launch(void* const* d_in, const int* in_sizes, int n_in,
                              void* d_out, int out_size)
{
    const float* I  = (const float*)d_in[0];
    const float* Wt = (const float*)d_in[1];
    float* out = (float*)d_out;

    const int S    = in_sizes[0] / T_STEPS;
    const int Wlen = in_sizes[1];

    const float coef = (float)(pow(0.1, 0.15) * tgamma(2.0 - 0.15) / 0.5);

    const int pairs = S / 2;                 // S = 2048 -> 1024 warp-blocks
    flif_kernel<<<pairs, 32>>>(I, Wt, out, S, Wlen, coef);
}